// round 8
// baseline (speedup 1.0000x reference)
#include <cuda_runtime.h>
#include <cstdint>

#define BATCH 16384
#define NN 32
#define NBLK (BATCH / 4)   // 4096 blocks, 4 warps (matrices) each

__device__ float        g_partial[3][NBLK];   // planar: coalesced tail reduction
__device__ unsigned int g_count = 0;

__device__ __forceinline__ float warp_sum(float x) {
#pragma unroll
    for (int o = 16; o > 0; o >>= 1) x += __shfl_xor_sync(0xffffffffu, x, o);
    return x;
}
__device__ __forceinline__ float warp_min(float x) {
#pragma unroll
    for (int o = 16; o > 0; o >>= 1) x = fminf(x, __shfl_xor_sync(0xffffffffu, x, o));
    return x;
}
__device__ __forceinline__ float warp_max(float x) {
#pragma unroll
    for (int o = 16; o > 0; o >>= 1) x = fmaxf(x, __shfl_xor_sync(0xffffffffu, x, o));
    return x;
}

// One warp per matrix. Matrix lives in registers (lane = row).
// launch_bounds(128, 8): cap regs at 64 -> 8 blocks/SM -> 50% occupancy.
__global__ __launch_bounds__(128, 8) void fused_kernel(
    const float4* __restrict__ pred4, const float4* __restrict__ tgt4,
    const float*  __restrict__ mask,  float* __restrict__ out)
{
    __shared__ __align__(16) float s_tr[4][NN * 33];  // transpose / tridiag scratch
    __shared__ __align__(16) float s_v [4][NN];
    __shared__ __align__(16) float s_q [4][NN];
    __shared__ float s_red[4][3];
    __shared__ float s_fr[3][4];
    __shared__ bool  s_last;

    const int warp = threadIdx.x >> 5;
    const int lane = threadIdx.x & 31;
    const int b    = (blockIdx.x << 2) + warp;

    float* tr = s_tr[warp];
    float* vb = s_v [warp];
    float* qb = s_q [warp];

    // ---- load own pred row into registers ----
    float a[NN];
    {
        const float4* prow = pred4 + (size_t)b * 256 + lane * 8;
#pragma unroll
        for (int j4 = 0; j4 < 8; j4++) {
            float4 v = prow[j4];
            a[4*j4+0] = v.x; a[4*j4+1] = v.y; a[4*j4+2] = v.z; a[4*j4+3] = v.w;
        }
    }
    float Dr = 0.f;
#pragma unroll
    for (int j = 0; j < NN; j++) Dr += a[j];

    // stage row to smem (33-pitch, conflict-free) for transpose + diag pick;
    // stage mask into vb for broadcast reads
    float m = mask[(b << 5) + lane];
    vb[lane] = m;
#pragma unroll
    for (int j = 0; j < NN; j++) tr[lane * 33 + j] = a[j];
    __syncwarp();

    // ---- BCE partial: row `lane`, tgt streamed, pred from regs ----
    float sb = 0.f;
    {
        const float4* trow = tgt4 + (size_t)b * 256 + lane * 8;
        const float4* m4   = (const float4*)vb;
#pragma unroll
        for (int j4 = 0; j4 < 8; j4++) {
            float4 t  = trow[j4];
            float4 mm = m4[j4];
            float p0 = a[4*j4+0], p1 = a[4*j4+1], p2 = a[4*j4+2], p3 = a[4*j4+3];
            float x0 = (t.x > 0.5f) ? p0 : 1.f - p0;
            float x1 = (t.y > 0.5f) ? p1 : 1.f - p1;
            float x2 = (t.z > 0.5f) ? p2 : 1.f - p2;
            float x3 = (t.w > 0.5f) ? p3 : 1.f - p3;
            sb += mm.x * (-__logf(x0)) + mm.y * (-__logf(x1))
                + mm.z * (-__logf(x2)) + mm.w * (-__logf(x3));
        }
        sb *= m;   // m_i factor for this row
    }
    sb = warp_sum(sb);
    float cntm  = warp_sum(m);
    float smask = cntm * cntm;

    // ---- build symmetrized Laplacian in registers ----
    const float jit  = 1e-5f + (float)lane * (9.0e-5f / 31.0f);
    float pii  = tr[lane * 33 + lane];
    float dval = Dr + jit - pii;
#pragma unroll
    for (int j = 0; j < NN; j++) {
        float c = tr[j * 33 + lane];                 // A[j][lane] (transpose)
        a[j] = (j == lane) ? dval : -0.5f * (a[j] + c);
    }
    __syncwarp();   // mask reads done; vb reused for Householder v

    // ---- Householder tridiagonalization, fully unrolled, register-resident ----
    float myd = 0.f, mye2 = 0.f;
#pragma unroll
    for (int k = 0; k < NN - 2; k++) {
        float x  = a[k];                              // A[lane][k], const reg index
        float xi = (lane > k) ? x : 0.f;
        float sigma = warp_sum(xi * xi);
        float x1 = __shfl_sync(0xffffffffu, xi, k + 1);
        float nrm   = sqrtf(sigma);
        float alpha = (x1 >= 0.f) ? -nrm : nrm;       // e[k]
        if (lane == k) { myd = x; mye2 = sigma; }     // d[k], e[k]^2

        float vi    = (lane == (k + 1)) ? (x1 - alpha) : xi;  // masked for lane<=k
        float denom = sigma - x1 * alpha;
        float tau   = (denom > 0.f) ? __fdividef(1.0f, denom) : 0.f;
        vb[lane] = vi;
        __syncwarp();

        const float4* vb4 = (const float4*)vb;
        float pj = 0.f;
#pragma unroll
        for (int j4 = (k + 1) >> 2; j4 < 8; j4++) {   // vb zero below k+1
            float4 vv = vb4[j4];
            pj += a[4*j4+0] * vv.x + a[4*j4+1] * vv.y
                + a[4*j4+2] * vv.z + a[4*j4+3] * vv.w;
        }
        pj = (lane > k) ? tau * pj : 0.f;             // mask q support
        float pv = warp_sum(pj * vi);
        float qj = fmaf(-0.5f * tau * pv, vi, pj);
        qb[lane] = qj;
        __syncwarp();

        const float4* qb4 = (const float4*)qb;
#pragma unroll
        for (int j4 = (k + 1) >> 2; j4 < 8; j4++) {
            float4 vv = vb4[j4];
            float4 qq = qb4[j4];
            a[4*j4+0] = fmaf(-vi, qq.x, fmaf(-qj, vv.x, a[4*j4+0]));
            a[4*j4+1] = fmaf(-vi, qq.y, fmaf(-qj, vv.y, a[4*j4+1]));
            a[4*j4+2] = fmaf(-vi, qq.z, fmaf(-qj, vv.z, a[4*j4+2]));
            a[4*j4+3] = fmaf(-vi, qq.w, fmaf(-qj, vv.w, a[4*j4+3]));
        }
        __syncwarp();   // before next iteration's vb overwrite
    }
    if (lane == NN - 2) {
        myd = a[NN - 2];
        float e = a[NN - 1];
        mye2 = e * e;
    }
    if (lane == NN - 1) { myd = a[NN - 1]; mye2 = 0.f; }

    // ---- publish tridiagonal, Sturm 33-section for lambda_2 ----
    tr[lane]      = myd;
    tr[NN + lane] = mye2;
    __syncwarp();

    float er  = sqrtf(mye2);
    float erp = __shfl_up_sync(0xffffffffu, er, 1);
    if (lane == 0) erp = 0.f;
    float rad = er + erp;
    float lo = warp_min(myd - rad) - 1e-3f;
    float hi = warp_max(myd + rad) + 1e-3f;

    // 5 iterations: width ~ 60/33^5 ~ 1.5e-6, far below the 1e-3 gate
    const float inv33 = 1.0f / 33.0f;
    for (int it = 0; it < 5; it++) {
        float w = hi - lo;
        float xx = fmaf(w, (float)(lane + 1) * inv33, lo);
        int cnt = 0;
        float q = tr[0] - xx;
        cnt += (q < 0.f);
#pragma unroll
        for (int i = 1; i < NN; i++) {
            if (q == 0.f) q = -1e-30f;
            q = tr[i] - xx - __fdividef(tr[NN + i - 1], q);
            cnt += (q < 0.f);
        }
        unsigned mm = __ballot_sync(0xffffffffu, cnt >= 2);
        if (mm == 0u) {
            lo = fmaf(w, 32.0f * inv33, lo);
        } else {
            int j = __ffs(mm) - 1;
            float nhi = fmaf(w, (float)(j + 1) * inv33, lo);
            float nlo = (j == 0) ? lo : fmaf(w, (float)j * inv33, lo);
            hi = nhi; lo = nlo;
        }
    }
    float lam2 = 0.5f * (lo + hi);

    if (lane == 0) {
        out[2 + b] = lam2;
        s_red[warp][0] = sb;
        s_red[warp][1] = smask;
        s_red[warp][2] = fmaxf(0.1f - lam2, 0.f);
    }
    __syncthreads();

    // ---- grid-wide scalar reduction via last-block pattern ----
    if (threadIdx.x == 0) {
        g_partial[0][blockIdx.x] = s_red[0][0] + s_red[1][0] + s_red[2][0] + s_red[3][0];
        g_partial[1][blockIdx.x] = s_red[0][1] + s_red[1][1] + s_red[2][1] + s_red[3][1];
        g_partial[2][blockIdx.x] = s_red[0][2] + s_red[1][2] + s_red[2][2] + s_red[3][2];
        __threadfence();
        unsigned v = atomicInc(&g_count, NBLK - 1);   // self-wrapping counter
        s_last = (v == NBLK - 1);
    }
    __syncthreads();

    if (s_last) {
        float r0 = 0.f, r1 = 0.f, r2 = 0.f;
        for (int i = threadIdx.x; i < NBLK; i += 128) {   // coalesced planar reads
            r0 += g_partial[0][i];
            r1 += g_partial[1][i];
            r2 += g_partial[2][i];
        }
        r0 = warp_sum(r0); r1 = warp_sum(r1); r2 = warp_sum(r2);
        int w2 = threadIdx.x >> 5, l2 = threadIdx.x & 31;
        if (l2 == 0) { s_fr[0][w2] = r0; s_fr[1][w2] = r1; s_fr[2][w2] = r2; }
        __syncthreads();
        if (threadIdx.x == 0) {
            float b0 = s_fr[0][0] + s_fr[0][1] + s_fr[0][2] + s_fr[0][3];
            float m0 = s_fr[1][0] + s_fr[1][1] + s_fr[1][2] + s_fr[1][3];
            float p0 = s_fr[2][0] + s_fr[2][1] + s_fr[2][2] + s_fr[2][3];
            if (m0 < 1.f) m0 = 1.f;
            out[0] = b0 / m0;
            out[1] = p0 / (float)BATCH;
        }
    }
}

extern "C" void kernel_launch(void* const* d_in, const int* in_sizes, int n_in,
                              void* d_out, int out_size)
{
    const float* pred = (const float*)d_in[0];
    const float* tgt  = (const float*)d_in[1];
    const float* mask = (const float*)d_in[2];
    float* out = (float*)d_out;

    fused_kernel<<<NBLK, 128>>>((const float4*)pred, (const float4*)tgt, mask, out);
}